// round 15
// baseline (speedup 1.0000x reference)
#include <cuda_runtime.h>
#include <math.h>

#define NQ       10
#define DIM      1024
#define NLAYERS  5
#define NU       ((NLAYERS + 1) * NQ)   // 60 variational gates
#define NUF      (NU * 8)               // 480 floats of gate matrices
#define WARPS    2
#define THREADS  (WARPS * 32)

// Precomputed variational gate matrices U = Rz(c)*Ry(b)*Rx(a), 8 floats each:
// u00r,u00i,u01r,u01i,u10r,u10i,u11r,u11i
__device__ float g_U[NUF];

// ---------------------------------------------------------------------------
// Prep kernel: build the 60 fused single-qubit matrices from theta.
// ---------------------------------------------------------------------------
__global__ void pqc_prep_kernel(const float* __restrict__ theta) {
    int i = blockIdx.x * blockDim.x + threadIdx.x;
    if (i >= NU) return;
    float a = theta[i * 3 + 0];
    float b = theta[i * 3 + 1];
    float c = theta[i * 3 + 2];
    float ca = cosf(0.5f * a), sa = sinf(0.5f * a);
    float cb = cosf(0.5f * b), sb = sinf(0.5f * b);
    float cc = cosf(0.5f * c), sc = sinf(0.5f * c);
    // M = Ry(b) * Rx(a)
    float m00r =  cb * ca, m00i =  sb * sa;
    float m01r = -sb * ca, m01i = -cb * sa;
    float m10r =  sb * ca, m10i = -cb * sa;
    float m11r =  cb * ca, m11i = -sb * sa;
    // U = Rz(c) * M : row0 *= (cc - i sc), row1 *= (cc + i sc)
    float* u = &g_U[i * 8];
    u[0] = m00r * cc + m00i * sc;  u[1] = m00i * cc - m00r * sc;
    u[2] = m01r * cc + m01i * sc;  u[3] = m01i * cc - m01r * sc;
    u[4] = m10r * cc - m10i * sc;  u[5] = m10i * cc + m10r * sc;
    u[6] = m11r * cc - m11i * sc;  u[7] = m11i * cc + m11r * sc;
}

// ---------------------------------------------------------------------------
// Gate on a register bit P (wires 5..9 map to index bits 4..0).
// ---------------------------------------------------------------------------
template<int P>
__device__ __forceinline__ void gate_reg(float* cr, float* ci, const float* g) {
    const float g0 = g[0], g1 = g[1], g2 = g[2], g3 = g[3];
    const float g4 = g[4], g5 = g[5], g6 = g[6], g7 = g[7];
#pragma unroll
    for (int base = 0; base < 32; ++base) {
        if (base & (1 << P)) continue;
        const int i0 = base, i1 = base | (1 << P);
        float a0r = cr[i0], a0i = ci[i0];
        float a1r = cr[i1], a1i = ci[i1];
        cr[i0] = g0 * a0r - g1 * a0i + g2 * a1r - g3 * a1i;
        ci[i0] = g0 * a0i + g1 * a0r + g2 * a1i + g3 * a1r;
        cr[i1] = g4 * a0r - g5 * a0i + g6 * a1r - g7 * a1i;
        ci[i1] = g4 * a0i + g5 * a0r + g6 * a1i + g7 * a1r;
    }
}

// ---------------------------------------------------------------------------
// Gate on a lane bit M (wires 0..4 map to lane bits 4..0).
// ---------------------------------------------------------------------------
template<int M>
__device__ __forceinline__ void gate_lane(float* cr, float* ci, const float* g, int lane) {
    const bool hi = (lane >> M) & 1;
    const float Ar = hi ? g[6] : g[0];
    const float Ai = hi ? g[7] : g[1];
    const float Br = hi ? g[4] : g[2];
    const float Bi = hi ? g[5] : g[3];
#pragma unroll
    for (int r = 0; r < 32; ++r) {
        float pr = __shfl_xor_sync(0xffffffffu, cr[r], 1 << M);
        float pi = __shfl_xor_sync(0xffffffffu, ci[r], 1 << M);
        float nr = Ar * cr[r] - Ai * ci[r] + Br * pr - Bi * pi;
        float ni = Ar * ci[r] + Ai * cr[r] + Br * pi + Bi * pr;
        cr[r] = nr; ci[r] = ni;
    }
}

// Build fused gate G = U(l,q) @ Rx(ang); U coefficients via uniform L1 loads.
__device__ __forceinline__ void build_g(float* g, int l, int q, float ang_half) {
    const float* u = &g_U[(l * NQ + q) * 8];
    float u0 = __ldg(u + 0), u1 = __ldg(u + 1), u2 = __ldg(u + 2), u3 = __ldg(u + 3);
    float u4 = __ldg(u + 4), u5 = __ldg(u + 5), u6 = __ldg(u + 6), u7 = __ldg(u + 7);
    float sg, cg;
    sincosf(ang_half, &sg, &cg);
    // Rx applied FIRST: G = U * Rx
    g[0] = cg * u0 + sg * u3;  g[1] = cg * u1 - sg * u2;
    g[2] = cg * u2 + sg * u1;  g[3] = cg * u3 - sg * u0;
    g[4] = cg * u4 + sg * u7;  g[5] = cg * u5 - sg * u6;
    g[6] = cg * u6 + sg * u5;  g[7] = cg * u7 - sg * u4;
}

// ---------------------------------------------------------------------------
// Main kernel: one WARP per batch element; state in registers (32 cplx/lane).
// Index k = (lane << 5) | r.  Wire q <-> index bit p = 9 - q.
// 64-thread CTAs, forced <=128 regs -> 8 CTAs (16 warps) per SM.
// ---------------------------------------------------------------------------
__global__ void __launch_bounds__(THREADS, 8)
pqc_warp_kernel(const float* __restrict__ x,
                const float* __restrict__ lam,
                const float* __restrict__ w,
                float* __restrict__ out,
                int B) {
    const int tid  = threadIdx.x;
    const int lane = tid & 31;
    const int b    = blockIdx.x * WARPS + (tid >> 5);
    if (b >= B) return;

    // --- CZ-ring diagonal sign mask for this lane's 32 register slots -----
    unsigned czmask = 0;
#pragma unroll
    for (int r = 0; r < 32; ++r) {
        int k   = (lane << 5) | r;
        int adj = k & (k >> 1);                           // adjacent-bit ring
        int par = (__popc(adj) + ((k >> 9) & k & 1)) & 1; // + (bit9 & bit0)
        czmask |= (unsigned)par << r;
    }

    // --- Layer 0 from |0...0>: tensor-product state, built directly -------
    float cr[32], ci[32];
    {
        float pr = 1.0f, pi = 0.0f;
#pragma unroll
        for (int m = 0; m < 5; ++m) {
            const float* u = &g_U[(4 - m) * 8];
            int bit = (lane >> m) & 1;
            float ur = __ldg(u + bit * 4 + 0), ui = __ldg(u + bit * 4 + 1);
            float nr = pr * ur - pi * ui;
            float ni = pr * ui + pi * ur;
            pr = nr; pi = ni;
        }
        cr[0] = pr; ci[0] = pi;
#pragma unroll
        for (int p = 0; p < 5; ++p) {
            const float* u = &g_U[(9 - p) * 8];
            float u0r = __ldg(u + 0), u0i = __ldg(u + 1);
            float u1r = __ldg(u + 4), u1i = __ldg(u + 5);
#pragma unroll
            for (int r = 0; r < (1 << p); ++r) {
                float ar = cr[r], ai = ci[r];
                cr[r | (1 << p)] = ar * u1r - ai * u1i;
                ci[r | (1 << p)] = ar * u1i + ai * u1r;
                cr[r] = ar * u0r - ai * u0i;
                ci[r] = ar * u0i + ai * u0r;
            }
        }
    }

    // CZ after layer 0
#pragma unroll
    for (int r = 0; r < 32; ++r) {
        unsigned s = ((czmask >> r) & 1u) << 31;
        cr[r] = __uint_as_float(__float_as_uint(cr[r]) ^ s);
        ci[r] = __uint_as_float(__float_as_uint(ci[r]) ^ s);
    }

    // --- Layers 1..5: fused gates G = U(l,q) @ Rx(x_q * lam[l-1,q]) -------
    const float* xb = &x[b * NQ];
#pragma unroll 1
    for (int l = 1; l <= NLAYERS; ++l) {
        const float* lm = &lam[(l - 1) * NQ];
        float g[8];
        // wires 0..4 -> lane bits 4..0
        build_g(g, l, 0, 0.5f * __ldg(xb + 0) * __ldg(lm + 0)); gate_lane<4>(cr, ci, g, lane);
        build_g(g, l, 1, 0.5f * __ldg(xb + 1) * __ldg(lm + 1)); gate_lane<3>(cr, ci, g, lane);
        build_g(g, l, 2, 0.5f * __ldg(xb + 2) * __ldg(lm + 2)); gate_lane<2>(cr, ci, g, lane);
        build_g(g, l, 3, 0.5f * __ldg(xb + 3) * __ldg(lm + 3)); gate_lane<1>(cr, ci, g, lane);
        build_g(g, l, 4, 0.5f * __ldg(xb + 4) * __ldg(lm + 4)); gate_lane<0>(cr, ci, g, lane);
        // wires 5..9 -> register bits 4..0
        build_g(g, l, 5, 0.5f * __ldg(xb + 5) * __ldg(lm + 5)); gate_reg<4>(cr, ci, g);
        build_g(g, l, 6, 0.5f * __ldg(xb + 6) * __ldg(lm + 6)); gate_reg<3>(cr, ci, g);
        build_g(g, l, 7, 0.5f * __ldg(xb + 7) * __ldg(lm + 7)); gate_reg<2>(cr, ci, g);
        build_g(g, l, 8, 0.5f * __ldg(xb + 8) * __ldg(lm + 8)); gate_reg<1>(cr, ci, g);
        build_g(g, l, 9, 0.5f * __ldg(xb + 9) * __ldg(lm + 9)); gate_reg<0>(cr, ci, g);
        if (l < NLAYERS) {   // CZ ring (final ring skipped: phase-only)
#pragma unroll
            for (int r = 0; r < 32; ++r) {
                unsigned s = ((czmask >> r) & 1u) << 31;
                cr[r] = __uint_as_float(__float_as_uint(cr[r]) ^ s);
                ci[r] = __uint_as_float(__float_as_uint(ci[r]) ^ s);
            }
        }
    }

    // --- <Z^{(x)10}> : sign = (-1)^popc(k) --------------------------------
    float sp = 0.0f, sn = 0.0f;
#pragma unroll
    for (int r = 0; r < 32; ++r) {
        float m2 = cr[r] * cr[r] + ci[r] * ci[r];
        if (__popc(r) & 1) sn += m2; else sp += m2;
    }
    float e = sp - sn;
    if (__popc(lane) & 1) e = -e;
#pragma unroll
    for (int off = 16; off; off >>= 1)
        e += __shfl_xor_sync(0xffffffffu, e, off);

    if (lane == 0) {
        float l0 = e * __ldg(w + 0), l1 = e * __ldg(w + 1);
        float m  = fmaxf(l0, l1);
        float e0 = expf(l0 - m), e1 = expf(l1 - m);
        float inv = 1.0f / (e0 + e1);
        out[2 * b + 0] = e0 * inv;
        out[2 * b + 1] = e1 * inv;
    }
}

// ---------------------------------------------------------------------------
extern "C" void kernel_launch(void* const* d_in, const int* in_sizes, int n_in,
                              void* d_out, int out_size) {
    const float* x     = (const float*)d_in[0];
    const float* theta = (const float*)d_in[1];
    const float* lam   = (const float*)d_in[2];
    const float* w     = (const float*)d_in[3];
    float* out = (float*)d_out;

    const int B = in_sizes[0] / NQ;   // 2048

    pqc_prep_kernel<<<1, 64>>>(theta);
    pqc_warp_kernel<<<(B + WARPS - 1) / WARPS, THREADS>>>(x, lam, w, out, B);
}

// round 16
// speedup vs baseline: 1.3391x; 1.3391x over previous
#include <cuda_runtime.h>
#include <math.h>

#define NQ       10
#define DIM      1024
#define NLAYERS  5
#define NU       ((NLAYERS + 1) * NQ)   // 60 variational gates
#define NUF      (NU * 8)               // 480 floats of gate matrices
#define NLAM     (NLAYERS * NQ)         // 50
#define WARPS    2
#define THREADS  (WARPS * 32)

typedef unsigned long long u64;

// Precomputed variational gate matrices U = Rz(c)*Ry(b)*Rx(a), 8 floats each:
// u00r,u00i,u01r,u01i,u10r,u10i,u11r,u11i
__device__ float g_U[NUF];

// ---------------------------------------------------------------------------
// Prep kernel: build the 60 fused single-qubit matrices from theta.
// ---------------------------------------------------------------------------
__global__ void pqc_prep_kernel(const float* __restrict__ theta) {
    int i = blockIdx.x * blockDim.x + threadIdx.x;
    if (i >= NU) return;
    float a = theta[i * 3 + 0];
    float b = theta[i * 3 + 1];
    float c = theta[i * 3 + 2];
    float ca = cosf(0.5f * a), sa = sinf(0.5f * a);
    float cb = cosf(0.5f * b), sb = sinf(0.5f * b);
    float cc = cosf(0.5f * c), sc = sinf(0.5f * c);
    // M = Ry(b) * Rx(a)
    float m00r =  cb * ca, m00i =  sb * sa;
    float m01r = -sb * ca, m01i = -cb * sa;
    float m10r =  sb * ca, m10i = -cb * sa;
    float m11r =  cb * ca, m11i = -sb * sa;
    // U = Rz(c) * M : row0 *= (cc - i sc), row1 *= (cc + i sc)
    float* u = &g_U[i * 8];
    u[0] = m00r * cc + m00i * sc;  u[1] = m00i * cc - m00r * sc;
    u[2] = m01r * cc + m01i * sc;  u[3] = m01i * cc - m01r * sc;
    u[4] = m10r * cc - m10i * sc;  u[5] = m10i * cc + m10r * sc;
    u[6] = m11r * cc - m11i * sc;  u[7] = m11i * cc + m11r * sc;
}

// --------------------------- f32x2 packed helpers --------------------------
__device__ __forceinline__ u64 pk1(float v) {
    u64 d; asm("mov.b64 %0, {%1, %1};" : "=l"(d) : "f"(v)); return d;
}
__device__ __forceinline__ u64 pk2(float a, float b) {
    u64 d; asm("mov.b64 %0, {%1, %2};" : "=l"(d) : "f"(a), "f"(b)); return d;
}
__device__ __forceinline__ void unpk(u64 v, float& a, float& b) {
    asm("mov.b64 {%0, %1}, %2;" : "=f"(a), "=f"(b) : "l"(v));
}
__device__ __forceinline__ u64 mul2(u64 a, u64 b) {
    u64 d; asm("mul.rn.f32x2 %0, %1, %2;" : "=l"(d) : "l"(a), "l"(b)); return d;
}
__device__ __forceinline__ u64 fma2(u64 a, u64 b, u64 c) {
    u64 d; asm("fma.rn.f32x2 %0, %1, %2, %3;" : "=l"(d) : "l"(a), "l"(b), "l"(c)); return d;
}

// ---------------------------------------------------------------------------
// State layout: amp index k = (lane << 5) | r, r = 2v + e. Lane holds
// CR[v]/CI[v] = packed (amp[2v], amp[2v+1]) real/imag. Wire q <-> bit 9-q:
// wires 0..4 -> lane bits 4..0, wires 5..8 -> vector bits 3..0, wire 9 -> e.
// ---------------------------------------------------------------------------

// Gate on vector bit VP (wires 5..8). Packed: 2 amps per op.
template<int VP>
__device__ __forceinline__ void gate_reg_p(u64* CR, u64* CI, const float* g) {
    u64 P0 = pk1(g[0]), P1 = pk1(g[1]), P2 = pk1(g[2]), P3 = pk1(g[3]);
    u64 P4 = pk1(g[4]), P5 = pk1(g[5]), P6 = pk1(g[6]), P7 = pk1(g[7]);
    u64 N1 = pk1(-g[1]), N3 = pk1(-g[3]), N5 = pk1(-g[5]), N7 = pk1(-g[7]);
#pragma unroll
    for (int vb = 0; vb < 16; ++vb) {
        if (vb & (1 << VP)) continue;
        const int v0 = vb, v1 = vb | (1 << VP);
        u64 AR = CR[v0], AI = CI[v0], BR = CR[v1], BI = CI[v1];
        u64 NR0 = fma2(N1, AI, mul2(P0, AR)); NR0 = fma2(P2, BR, NR0); NR0 = fma2(N3, BI, NR0);
        u64 NI0 = fma2(P0, AI, mul2(P1, AR)); NI0 = fma2(P3, BR, NI0); NI0 = fma2(P2, BI, NI0);
        u64 NR1 = fma2(N5, AI, mul2(P4, AR)); NR1 = fma2(P6, BR, NR1); NR1 = fma2(N7, BI, NR1);
        u64 NI1 = fma2(P4, AI, mul2(P5, AR)); NI1 = fma2(P7, BR, NI1); NI1 = fma2(P6, BI, NI1);
        CR[v0] = NR0; CI[v0] = NI0; CR[v1] = NR1; CI[v1] = NI1;
    }
}

// Gate on the packed (intra-pair) bit = wire 9. Scalar on unpacked halves.
__device__ __forceinline__ void gate_reg0_p(u64* CR, u64* CI, const float* g) {
    const float g0 = g[0], g1 = g[1], g2 = g[2], g3 = g[3];
    const float g4 = g[4], g5 = g[5], g6 = g[6], g7 = g[7];
#pragma unroll
    for (int v = 0; v < 16; ++v) {
        float a0r, a1r, a0i, a1i;
        unpk(CR[v], a0r, a1r); unpk(CI[v], a0i, a1i);
        float n0r = g0 * a0r - g1 * a0i + g2 * a1r - g3 * a1i;
        float n0i = g1 * a0r + g0 * a0i + g3 * a1r + g2 * a1i;
        float n1r = g4 * a0r - g5 * a0i + g6 * a1r - g7 * a1i;
        float n1i = g5 * a0r + g4 * a0i + g7 * a1r + g6 * a1i;
        CR[v] = pk2(n0r, n1r); CI[v] = pk2(n0i, n1i);
    }
}

// Gate on lane bit M (wires 0..4). shfl.xor halves, packed FMAs.
template<int M>
__device__ __forceinline__ void gate_lane_p(u64* CR, u64* CI, const float* g, int lane) {
    const bool hi = (lane >> M) & 1;
    const float Ar = hi ? g[6] : g[0];
    const float Ai = hi ? g[7] : g[1];
    const float Br = hi ? g[4] : g[2];
    const float Bi = hi ? g[5] : g[3];
    u64 PAr = pk1(Ar), PAi = pk1(Ai), PnAi = pk1(-Ai);
    u64 PBr = pk1(Br), PBi = pk1(Bi), PnBi = pk1(-Bi);
#pragma unroll
    for (int v = 0; v < 16; ++v) {
        float c0, c1, d0, d1;
        unpk(CR[v], c0, c1); unpk(CI[v], d0, d1);
        float p0 = __shfl_xor_sync(0xffffffffu, c0, 1 << M);
        float p1 = __shfl_xor_sync(0xffffffffu, c1, 1 << M);
        float q0 = __shfl_xor_sync(0xffffffffu, d0, 1 << M);
        float q1 = __shfl_xor_sync(0xffffffffu, d1, 1 << M);
        u64 PR = pk2(p0, p1), PI = pk2(q0, q1);
        u64 NR = fma2(PnAi, CI[v], mul2(PAr, CR[v]));
        NR = fma2(PBr, PR, NR); NR = fma2(PnBi, PI, NR);
        u64 NI = fma2(PAr, CI[v], mul2(PAi, CR[v]));
        NI = fma2(PBi, PR, NI); NI = fma2(PBr, PI, NI);
        CR[v] = NR; CI[v] = NI;
    }
}

// Build fused gate G = U(l,q) @ Rx(ang) from smem coefficients.
__device__ __forceinline__ void build_g(float* g, const float* __restrict__ sU,
                                        int l, int q, float ang_half) {
    const float* u = &sU[(l * NQ + q) * 8];
    float sg, cg;
    sincosf(ang_half, &sg, &cg);
    g[0] = cg * u[0] + sg * u[3];  g[1] = cg * u[1] - sg * u[2];
    g[2] = cg * u[2] + sg * u[1];  g[3] = cg * u[3] - sg * u[0];
    g[4] = cg * u[4] + sg * u[7];  g[5] = cg * u[5] - sg * u[6];
    g[6] = cg * u[6] + sg * u[5];  g[7] = cg * u[7] - sg * u[4];
}

// ---------------------------------------------------------------------------
// Main kernel: one WARP per batch element; packed register-resident state.
// ---------------------------------------------------------------------------
__global__ void __launch_bounds__(THREADS)
pqc_warp_kernel(const float* __restrict__ x,
                const float* __restrict__ lam,
                const float* __restrict__ w,
                float* __restrict__ out,
                int B) {
    __shared__ float sU[NUF];
    __shared__ float sLam[NLAM];

    const int tid  = threadIdx.x;
    const int lane = tid & 31;
    const int b    = blockIdx.x * WARPS + (tid >> 5);

    for (int i = tid; i < NUF; i += THREADS) sU[i] = g_U[i];
    for (int i = tid; i < NLAM; i += THREADS) sLam[i] = lam[i];
    __syncthreads();
    if (b >= B) return;

    // --- CZ-ring diagonal parity mask for this lane's 32 amp slots --------
    unsigned czmask = 0;
#pragma unroll
    for (int r = 0; r < 32; ++r) {
        int k   = (lane << 5) | r;
        int adj = k & (k >> 1);                           // adjacent-bit ring
        int par = (__popc(adj) + ((k >> 9) & k & 1)) & 1; // + (bit9 & bit0)
        czmask |= (unsigned)par << r;
    }

    // --- Layer 0 from |0...0>: tensor-product state, built directly -------
    u64 CR[16], CI[16];
    {
        float pr = 1.0f, pi = 0.0f;
#pragma unroll
        for (int m = 0; m < 5; ++m) {            // lane-bit wires (wire 4-m)
            const float* u = &sU[(4 - m) * 8];
            int bit = (lane >> m) & 1;
            float ur = u[bit * 4 + 0], ui = u[bit * 4 + 1];
            float nr = pr * ur - pi * ui;
            float ni = pr * ui + pi * ur;
            pr = nr; pi = ni;
        }
        // wire 9 -> intra-pair slot
        {
            const float* u = &sU[9 * 8];
            float a0r = pr * u[0] - pi * u[1];
            float a0i = pr * u[1] + pi * u[0];
            float a1r = pr * u[4] - pi * u[5];
            float a1i = pr * u[5] + pi * u[4];
            CR[0] = pk2(a0r, a1r); CI[0] = pk2(a0i, a1i);
        }
        // wires 8..5 -> vector bits 0..3 (doubling, packed complex mult)
#pragma unroll
        for (int p = 1; p < 5; ++p) {
            const float* u = &sU[(9 - p) * 8];
            u64 U0r = pk1(u[0]), U0i = pk1(u[1]), N0i = pk1(-u[1]);
            u64 U1r = pk1(u[4]), U1i = pk1(u[5]), N1i = pk1(-u[5]);
            const int vb = p - 1;
#pragma unroll
            for (int v = 0; v < (1 << vb); ++v) {
                u64 ar = CR[v], ai = CI[v];
                CR[v | (1 << vb)] = fma2(N1i, ai, mul2(U1r, ar));
                CI[v | (1 << vb)] = fma2(U1r, ai, mul2(U1i, ar));
                CR[v] = fma2(N0i, ai, mul2(U0r, ar));
                CI[v] = fma2(U0r, ai, mul2(U0i, ar));
            }
        }
    }

    // CZ after layer 0
#pragma unroll
    for (int v = 0; v < 16; ++v) {
        u64 m = ((u64)((czmask >> (2 * v)) & 1u) << 31)
              | ((u64)((czmask >> (2 * v + 1)) & 1u) << 63);
        CR[v] ^= m; CI[v] ^= m;
    }

    // --- Layers 1..5: fused gates G = U(l,q) @ Rx(x_q * lam[l-1,q]) -------
    const float* xb = &x[b * NQ];
#pragma unroll 1
    for (int l = 1; l <= NLAYERS; ++l) {
        const float* lm = &sLam[(l - 1) * NQ];
        float g[8];
        // wires 0..4 -> lane bits 4..0
        build_g(g, sU, l, 0, 0.5f * xb[0] * lm[0]); gate_lane_p<4>(CR, CI, g, lane);
        build_g(g, sU, l, 1, 0.5f * xb[1] * lm[1]); gate_lane_p<3>(CR, CI, g, lane);
        build_g(g, sU, l, 2, 0.5f * xb[2] * lm[2]); gate_lane_p<2>(CR, CI, g, lane);
        build_g(g, sU, l, 3, 0.5f * xb[3] * lm[3]); gate_lane_p<1>(CR, CI, g, lane);
        build_g(g, sU, l, 4, 0.5f * xb[4] * lm[4]); gate_lane_p<0>(CR, CI, g, lane);
        // wires 5..8 -> vector bits 3..0
        build_g(g, sU, l, 5, 0.5f * xb[5] * lm[5]); gate_reg_p<3>(CR, CI, g);
        build_g(g, sU, l, 6, 0.5f * xb[6] * lm[6]); gate_reg_p<2>(CR, CI, g);
        build_g(g, sU, l, 7, 0.5f * xb[7] * lm[7]); gate_reg_p<1>(CR, CI, g);
        build_g(g, sU, l, 8, 0.5f * xb[8] * lm[8]); gate_reg_p<0>(CR, CI, g);
        // wire 9 -> intra-pair
        build_g(g, sU, l, 9, 0.5f * xb[9] * lm[9]); gate_reg0_p(CR, CI, g);
        if (l < NLAYERS) {   // CZ ring (final ring skipped: phase-only)
#pragma unroll
            for (int v = 0; v < 16; ++v) {
                u64 m = ((u64)((czmask >> (2 * v)) & 1u) << 31)
                      | ((u64)((czmask >> (2 * v + 1)) & 1u) << 63);
                CR[v] ^= m; CI[v] ^= m;
            }
        }
    }

    // --- <Z^{(x)10}> : sign = (-1)^{popc(lane)+popc(r)}; popc(2v)=popc(v) --
    float e = 0.0f;
#pragma unroll
    for (int v = 0; v < 16; ++v) {
        float a0r, a1r, a0i, a1i;
        unpk(CR[v], a0r, a1r); unpk(CI[v], a0i, a1i);
        float m0 = a0r * a0r + a0i * a0i;
        float m1 = a1r * a1r + a1i * a1i;
        e += (__popc(v) & 1) ? (m1 - m0) : (m0 - m1);
    }
    if (__popc(lane) & 1) e = -e;
#pragma unroll
    for (int off = 16; off; off >>= 1)
        e += __shfl_xor_sync(0xffffffffu, e, off);

    if (lane == 0) {
        float l0 = e * w[0], l1 = e * w[1];
        float m  = fmaxf(l0, l1);
        float e0 = expf(l0 - m), e1 = expf(l1 - m);
        float inv = 1.0f / (e0 + e1);
        out[2 * b + 0] = e0 * inv;
        out[2 * b + 1] = e1 * inv;
    }
}

// ---------------------------------------------------------------------------
extern "C" void kernel_launch(void* const* d_in, const int* in_sizes, int n_in,
                              void* d_out, int out_size) {
    const float* x     = (const float*)d_in[0];
    const float* theta = (const float*)d_in[1];
    const float* lam   = (const float*)d_in[2];
    const float* w     = (const float*)d_in[3];
    float* out = (float*)d_out;

    const int B = in_sizes[0] / NQ;   // 2048

    pqc_prep_kernel<<<1, 64>>>(theta);
    pqc_warp_kernel<<<(B + WARPS - 1) / WARPS, THREADS>>>(x, lam, w, out, B);
}